// round 3
// baseline (speedup 1.0000x reference)
#include <cuda_runtime.h>
#include <math.h>
#include <float.h>

#define B_DIM  256
#define T_DIM  150
#define J_DIM  25
#define FEAT   9
#define SPLIT  6
#define TCHUNK (T_DIM / SPLIT)          // 25 timesteps per block
#define TPB    125                      // 125 = 5 * 25 -> j = tid%25 constant
#define NITEMS 5                        // items per thread
#define ITEMS  (TCHUNK * J_DIM)         // 625
#define OUTB   (J_DIM * FEAT)           // 225
#define JW     (2 * J_DIM)              // duplicated row width

__device__ float    g_scratch[B_DIM][SPLIT][OUTB];
__device__ unsigned g_ticket[B_DIM];    // zero-init; self-resetting

__device__ __forceinline__ float asqrt(float x) {
    float r;
    asm("sqrt.approx.f32 %0, %1;" : "=f"(r) : "f"(x));
    return r;
}

__global__ __launch_bounds__(TPB, 10)
void knn_feat_kernel(const float* __restrict__ x, float* __restrict__ out) {
    __shared__ float4 spos[TCHUNK][JW];   // 25*50*16 = 20000 B
    __shared__ float  spart[OUTB];
    __shared__ bool   s_last;

    const int b   = blockIdx.x;
    const int s   = blockIdx.y;
    const int tid = threadIdx.x;

    // cooperative load: 625 joints, duplicated row for rotated indexing
    const float* xb = x + ((size_t)b * T_DIM + s * TCHUNK) * (J_DIM * 3);
    for (int i = tid; i < ITEMS; i += TPB) {
        float px = xb[3 * i + 0];
        float py = xb[3 * i + 1];
        float pz = xb[3 * i + 2];
        float pp = fmaf(px, px, fmaf(py, py, pz * pz));
        float4 v = make_float4(px, py, pz, pp);
        int lt = i / J_DIM, j = i % J_DIM;
        spos[lt][j]         = v;
        spos[lt][j + J_DIM] = v;
    }
    for (int i = tid; i < OUTB; i += TPB) spart[i] = 0.0f;
    __syncthreads();

    const int jidx = tid % J_DIM;   // constant per thread
    const int ltb  = tid / J_DIM;   // 0..4

    float acc[FEAT];
#pragma unroll
    for (int f = 0; f < FEAT; ++f) acc[f] = 0.0f;

#pragma unroll
    for (int it = 0; it < NITEMS; ++it) {
        const int lt = ltb + it * (TCHUNK / NITEMS);
        const float4 p = spos[lt][jidx];
        const float px2 = -2.0f * p.x;
        const float py2 = -2.0f * p.y;
        const float pz2 = -2.0f * p.z;
        const float pp  = p.w;
        const float4* __restrict__ qrow = &spos[lt][jidx + 1];

        float m0 = FLT_MAX, m1 = FLT_MAX, m2 = FLT_MAX, m3 = FLT_MAX;
#pragma unroll
        for (int stp = 0; stp < J_DIM - 1; ++stp) {
            float4 q = qrow[stp];
            float sq = fmaf(pz2, q.z,
                        fmaf(py2, q.y,
                         fmaf(px2, q.x, pp + q.w)));
            float hi;
            hi = fmaxf(sq, m0); m0 = fminf(sq, m0); sq = hi;
            hi = fmaxf(sq, m1); m1 = fminf(sq, m1); sq = hi;
            hi = fmaxf(sq, m2); m2 = fminf(sq, m2); sq = hi;
            m3 = fminf(sq, m3);
        }

        const float d1 = asqrt(fmaxf(m0, 0.0f));
        const float d2 = asqrt(fmaxf(m1, 0.0f));
        const float d3 = asqrt(fmaxf(m2, 0.0f));
        const float d4 = asqrt(fmaxf(m3, 0.0f));

        // k = 2
        const float a2 = 0.5f * (d1 + d2);
        const float s2 = fabsf(d2 - d1) * 0.70710678118654752f;
        // k = 3
        const float a3 = (d1 + d2 + d3) * (1.0f / 3.0f);
        const float e1 = d1 - a3, e2 = d2 - a3, e3 = d3 - a3;
        const float s3 = asqrt(fmaf(e1, e1, fmaf(e2, e2, e3 * e3)) * 0.5f);
        // k = 4
        const float a4 = (d1 + d2 + d3 + d4) * 0.25f;
        const float g1 = d1 - a4, g2 = d2 - a4, g3 = d3 - a4, g4 = d4 - a4;
        const float s4 = asqrt(fmaf(g1, g1, fmaf(g2, g2, fmaf(g3, g3, g4 * g4)))
                               * (1.0f / 3.0f));

        acc[0] += a2; acc[1] += s2; acc[2] += d1;
        acc[3] += a3; acc[4] += s3; acc[5] += d1;
        acc[6] += a4; acc[7] += s4; acc[8] += d1;
    }

    // combine the 5 threads sharing each j (SMEM atomics, spread addresses)
#pragma unroll
    for (int f = 0; f < FEAT; ++f)
        atomicAdd(&spart[jidx * FEAT + f], acc[f]);
    __syncthreads();

    // publish this split's partial
    for (int i = tid; i < OUTB; i += TPB)
        g_scratch[b][s][i] = spart[i];
    __threadfence();
    __syncthreads();

    if (tid == 0) {
        unsigned old = atomicAdd(&g_ticket[b], 1u);
        s_last = (old == SPLIT - 1);
        if (s_last) g_ticket[b] = 0;   // self-reset for next graph replay
    }
    __syncthreads();

    if (s_last) {
        __threadfence();
        for (int i = tid; i < OUTB; i += TPB) {
            float sum = 0.0f;
#pragma unroll
            for (int k = 0; k < SPLIT; ++k)
                sum += g_scratch[b][k][i];
            out[(size_t)b * OUTB + i] = sum * (1.0f / (float)T_DIM);
        }
    }
}

extern "C" void kernel_launch(void* const* d_in, const int* in_sizes, int n_in,
                              void* d_out, int out_size) {
    const float* x = (const float*)d_in[0];
    float* out = (float*)d_out;
    dim3 grid(B_DIM, SPLIT);
    knn_feat_kernel<<<grid, TPB>>>(x, out);
}

// round 4
// speedup vs baseline: 1.0612x; 1.0612x over previous
#include <cuda_runtime.h>
#include <math.h>
#include <float.h>

#define B_DIM  256
#define T_DIM  150
#define J_DIM  25
#define FEAT   9
#define NACC   7                        // S1..S4, Vs2, Vs3, Vs4
#define SPLIT  3
#define TCHUNK (T_DIM / SPLIT)          // 50 timesteps per block
#define TPB    250                      // j = tid%25 constant per thread
#define NITEMS 5                        // (50*25)/250
#define ITEMS  (TCHUNK * J_DIM)         // 1250
#define OUTB   (J_DIM * FEAT)           // 225
#define PARTB  (J_DIM * NACC)           // 175

__device__ float    g_scratch[B_DIM][SPLIT][PARTB];
__device__ unsigned g_ticket[B_DIM];    // zero-init; self-resetting

__device__ __forceinline__ float asqrt(float x) {
    float r;
    asm("sqrt.approx.f32 %0, %1;" : "=f"(r) : "f"(x));
    return r;
}

__global__ __launch_bounds__(TPB, 5)
void knn_feat_kernel(const float* __restrict__ x, float* __restrict__ out) {
    __shared__ float4 spos[TCHUNK][J_DIM];   // 50*25*16 = 20000 B
    __shared__ float  spart[PARTB];
    __shared__ float  sfin[PARTB];
    __shared__ bool   s_last;

    const int b   = blockIdx.x;
    const int s   = blockIdx.y;
    const int tid = threadIdx.x;

    // cooperative load of 50x25 positions; w slot = |q|^2
    const float* xb = x + ((size_t)b * T_DIM + s * TCHUNK) * (J_DIM * 3);
    for (int i = tid; i < ITEMS; i += TPB) {
        float px = xb[3 * i + 0];
        float py = xb[3 * i + 1];
        float pz = xb[3 * i + 2];
        float pp = fmaf(px, px, fmaf(py, py, pz * pz));
        spos[i / J_DIM][i % J_DIM] = make_float4(px, py, pz, pp);
    }
    for (int i = tid; i < PARTB; i += TPB) spart[i] = 0.0f;
    __syncthreads();

    const int jidx = tid % J_DIM;   // constant per thread
    const int ltb  = tid / J_DIM;   // 0..9

    float S1 = 0.f, S2 = 0.f, S3 = 0.f, S4 = 0.f;
    float V2 = 0.f, V3 = 0.f, V4 = 0.f;

#pragma unroll
    for (int it = 0; it < NITEMS; ++it) {
        const int lt = ltb + it * 10;
        const float4 p = spos[lt][jidx];
        const float px2 = -2.0f * p.x;
        const float py2 = -2.0f * p.y;
        const float pz2 = -2.0f * p.z;
        const float pp  = p.w;

        float m0 = FLT_MAX, m1 = FLT_MAX, m2 = FLT_MAX, m3 = FLT_MAX;
#pragma unroll
        for (int j = 0; j < J_DIM; ++j) {
            float4 q = spos[lt][j];   // broadcast within warp (<=2 addrs)
            float sq = fmaf(pz2, q.z,
                        fmaf(py2, q.y,
                         fmaf(px2, q.x, pp + q.w)));
            sq = (j == jidx) ? FLT_MAX : sq;   // mask self
            float hi;
            hi = fmaxf(sq, m0); m0 = fminf(sq, m0); sq = hi;
            hi = fmaxf(sq, m1); m1 = fminf(sq, m1); sq = hi;
            hi = fmaxf(sq, m2); m2 = fminf(sq, m2); sq = hi;
            m3 = fminf(sq, m3);
        }

        const float d1 = asqrt(fmaxf(m0, 0.0f));
        const float d2 = asqrt(fmaxf(m1, 0.0f));
        const float d3 = asqrt(fmaxf(m2, 0.0f));
        const float d4 = asqrt(fmaxf(m3, 0.0f));

        // std features (two-pass form, numerically safe)
        const float s2 = fabsf(d2 - d1) * 0.70710678118654752f;
        const float a3 = (d1 + d2 + d3) * (1.0f / 3.0f);
        const float e1 = d1 - a3, e2 = d2 - a3, e3 = d3 - a3;
        const float s3 = asqrt(fmaf(e1, e1, fmaf(e2, e2, e3 * e3)) * 0.5f);
        const float a4 = (d1 + d2 + d3 + d4) * 0.25f;
        const float g1 = d1 - a4, g2 = d2 - a4, g3 = d3 - a4, g4 = d4 - a4;
        const float s4 = asqrt(fmaf(g1, g1, fmaf(g2, g2, fmaf(g3, g3, g4 * g4)))
                               * (1.0f / 3.0f));

        S1 += d1; S2 += d2; S3 += d3; S4 += d4;
        V2 += s2; V3 += s3; V4 += s4;
    }

    // combine the 10 threads sharing each j (SMEM atomics, spread addresses)
    atomicAdd(&spart[jidx * NACC + 0], S1);
    atomicAdd(&spart[jidx * NACC + 1], S2);
    atomicAdd(&spart[jidx * NACC + 2], S3);
    atomicAdd(&spart[jidx * NACC + 3], S4);
    atomicAdd(&spart[jidx * NACC + 4], V2);
    atomicAdd(&spart[jidx * NACC + 5], V3);
    atomicAdd(&spart[jidx * NACC + 6], V4);
    __syncthreads();

    // publish this split's partial
    for (int i = tid; i < PARTB; i += TPB)
        g_scratch[b][s][i] = spart[i];
    __threadfence();
    __syncthreads();

    if (tid == 0) {
        unsigned old = atomicAdd(&g_ticket[b], 1u);
        s_last = (old == SPLIT - 1);
        if (s_last) g_ticket[b] = 0;   // self-reset for next graph replay
    }
    __syncthreads();

    if (s_last) {
        __threadfence();
        // sum the split partials
        for (int i = tid; i < PARTB; i += TPB) {
            float sum = 0.0f;
#pragma unroll
            for (int k = 0; k < SPLIT; ++k)
                sum += g_scratch[b][k][i];
            sfin[i] = sum;
        }
        __syncthreads();
        // reconstruct the 9 features per joint from the 7 sums
        if (tid < OUTB) {
            const int j = tid / FEAT;
            const int f = tid % FEAT;
            const float* a = &sfin[j * NACC];
            const float t1 = a[0], t2 = a[1], t3 = a[2], t4 = a[3];
            float v;
            switch (f) {
                case 0: v = (t1 + t2) * 0.5f;               break;
                case 1: v = a[4];                           break;
                case 2: v = t1;                             break;
                case 3: v = (t1 + t2 + t3) * (1.f / 3.f);   break;
                case 4: v = a[5];                           break;
                case 5: v = t1;                             break;
                case 6: v = (t1 + t2 + t3 + t4) * 0.25f;    break;
                case 7: v = a[6];                           break;
                default: v = t1;                            break;
            }
            out[(size_t)b * OUTB + tid] = v * (1.0f / (float)T_DIM);
        }
    }
}

extern "C" void kernel_launch(void* const* d_in, const int* in_sizes, int n_in,
                              void* d_out, int out_size) {
    const float* x = (const float*)d_in[0];
    float* out = (float*)d_out;
    dim3 grid(B_DIM, SPLIT);
    knn_feat_kernel<<<grid, TPB>>>(x, out);
}